// round 17
// baseline (speedup 1.0000x reference)
#include <cuda_runtime.h>
#include <math.h>

#define NQ 4
#define DIM 16
#define NB 4
#define SS 512
#define EE 512
#define NTOK (NB*SS)           // 2048
#define OUT_ELEMS (NB*SS*EE)   // 1048576

// ---------------- scratch (no device allocation allowed) ----------------
__device__ float4 g_q4[NTOK];      // holds tanh(tanh-proj q) per token
__device__ float4 g_k4[NTOK];      // holds tanh(tanh-proj k) per token
__device__ float4 g_v4[NTOK];
__device__ float4 g_C4[27];        // staging: written by setup
__device__ float4 g_Wo4[EE];       // transposed Wout: g_Wo4[e] = Wout[0..3][e]
__constant__ float4 c_C4[27];      // broadcast path (memcpy'd between launches)

// ---------------- complex helpers ----------------
__device__ __forceinline__ float2 cmul(float2 a, float2 b) {
    return make_float2(a.x * b.x - a.y * b.y, a.x * b.y + a.y * b.x);
}
__device__ __forceinline__ float2 cadd(float2 a, float2 b) {
    return make_float2(a.x + b.x, a.y + b.y);
}

// ============================================================
// Barrier-free setup: ONE warp builds the circuit unitary.
// Column independence: all gates/CNOTs act within a column of U,
// so lane p evolves column p entirely in registers. Only
// __syncwarp()s; no block barriers.
// ============================================================
__device__ void do_setup_warp(const float* __restrict__ qw) {
    __shared__ float2 Gs[8][4];
    __shared__ float2 Ush[DIM][DIM + 1];   // [d][p]
    __shared__ float  Mre_s[DIM][DIM + 1];
    __shared__ float  Ctmp[81];

    int lane = threadIdx.x;   // 0..31 (only warp 0 calls this)

    // lanes 0..7: compute the 8 rot-gate matrices in parallel
    if (lane < 8) {
        float a = qw[lane * 3 + 0] * 0.5f;
        float b = qw[lane * 3 + 1] * 0.5f;
        float c = qw[lane * 3 + 2] * 0.5f;
        float ca, sa, cb, sb, cc, sc;
        sincosf(a, &sa, &ca);
        sincosf(b, &sb, &cb);
        sincosf(c, &sc, &cc);
        float2 m00 = make_float2( cb * ca,  sb * sa);
        float2 m01 = make_float2(-sb * ca, -cb * sa);
        float2 m10 = make_float2( sb * ca, -cb * sa);
        float2 m11 = make_float2( cb * ca, -sb * sa);
        float2 ezm = make_float2(cc, -sc);
        float2 ezp = make_float2(cc,  sc);
        Gs[lane][0] = cmul(ezm, m00); Gs[lane][1] = cmul(ezm, m01);
        Gs[lane][2] = cmul(ezp, m10); Gs[lane][3] = cmul(ezp, m11);
    }
    __syncwarp();

    // lanes 0..15: evolve column p = lane in registers
    float2 Ur[DIM];
    int p = lane;
    #pragma unroll
    for (int d = 0; d < DIM; d++)
        Ur[d] = make_float2(d == p ? 1.f : 0.f, 0.f);

    if (lane < DIM) {
        #pragma unroll
        for (int layer = 0; layer < 2; layer++) {
            #pragma unroll
            for (int w = 0; w < NQ; w++) {
                const int m = 8 >> w;               // wire0 = MSB
                float2 g00 = Gs[layer * 4 + w][0];
                float2 g01 = Gs[layer * 4 + w][1];
                float2 g10 = Gs[layer * 4 + w][2];
                float2 g11 = Gs[layer * 4 + w][3];
                #pragma unroll
                for (int i = 0; i < DIM; i++) {
                    if (i & m) continue;            // compile-time after unroll
                    const int j = i | m;
                    float2 x0 = Ur[i], x1 = Ur[j];
                    Ur[i] = cadd(cmul(g00, x0), cmul(g01, x1));
                    Ur[j] = cadd(cmul(g10, x0), cmul(g11, x1));
                }
            }
            // fused CNOT ring permutation (compile-time source indices)
            float2 tmp[DIM];
            #pragma unroll
            for (int d = 0; d < DIM; d++) {
                int i = d;
                i = (i & 1) ? (i ^ 8) : i;   // C(3,0)
                i = (i & 2) ? (i ^ 1) : i;   // C(2,3)
                i = (i & 4) ? (i ^ 2) : i;   // C(1,2)
                i = (i & 8) ? (i ^ 4) : i;   // C(0,1)
                tmp[d] = Ur[i];
            }
            #pragma unroll
            for (int d = 0; d < DIM; d++) Ur[d] = tmp[d];
        }
        // spill final U to shared
        #pragma unroll
        for (int d = 0; d < DIM; d++) Ush[d][p] = Ur[d];
    }
    __syncwarp();

    // Mre[p][q] = Re( sum_d conj(U[d][p]) z[d] U[d][q] ), 8 entries/lane
    #pragma unroll
    for (int r = 0; r < 8; r++) {
        int idx = lane * 8 + r;
        int pp = idx >> 4, qq = idx & 15;
        float s = 0.f;
        #pragma unroll
        for (int d = 0; d < DIM; d++) {
            float z = (float)(NQ - 2 * __popc(d));
            s += z * (Ush[d][pp].x * Ush[d][qq].x + Ush[d][pp].y * Ush[d][qq].y);
        }
        Mre_s[pp][qq] = s;
    }
    __syncwarp();

    // C tensor: 81 monomials, 16 nonzero (p,q) pairs each
    #pragma unroll
    for (int r = 0; r < 3; r++) {
        int t = lane + 32 * r;
        if (t < 81) {
            int dg[4];
            dg[0] = t / 27; dg[1] = (t / 9) % 3; dg[2] = (t / 3) % 3; dg[3] = t % 3;
            float acc = 0.f;
            #pragma unroll
            for (int c = 0; c < 16; c++) {
                int pp = 0, qq = 0;
                float sign = 1.f;
                #pragma unroll
                for (int w = 0; w < 4; w++) {
                    int cw = (c >> w) & 1;
                    int md = dg[w];
                    int pb, qb;
                    if (md == 1) { pb = cw; qb = cw ^ 1; }
                    else         { pb = cw; qb = cw; if (md == 0 && cw) sign = -sign; }
                    pp |= pb << (3 - w);
                    qq |= qb << (3 - w);
                }
                acc += sign * Mre_s[pp][qq];
            }
            // (1/2)^4 half-angle * 0.5 softmax scale
            Ctmp[t] = acc * 0.03125f;
        }
    }
    __syncwarp();
    if (lane < 27)
        g_C4[lane] = make_float4(Ctmp[3 * lane], Ctmp[3 * lane + 1],
                                 Ctmp[3 * lane + 2], 0.f);
}

// exp-based tanh: accurate to ~1e-7 relative
__device__ __forceinline__ float ftanh(float x) {
    float e = __expf(2.f * x);
    return __fdividef(e - 1.f, e + 1.f);
}

// ============================================================
// Kernel 1: q/k/v projections, warp-per-token (8 tokens/block),
// blocks 1..256. Block 0: warp 0 = setup, threads 32+ = Wout
// transpose. Stores tanh(q), tanh(k) for the tanh identity.
// ============================================================
__global__ __launch_bounds__(256)
void qkv_kernel(const float* __restrict__ x,
                const float* __restrict__ Wq, const float* __restrict__ bq,
                const float* __restrict__ Wk, const float* __restrict__ bk,
                const float* __restrict__ Wv, const float* __restrict__ bv,
                const float* __restrict__ qw,
                const float* __restrict__ Wout) {
    if (blockIdx.x == 0) {
        if (threadIdx.x < 32) {
            do_setup_warp(qw);
        } else {
            for (int e = threadIdx.x - 32; e < EE; e += 224)
                g_Wo4[e] = make_float4(Wout[e], Wout[EE + e],
                                       Wout[2 * EE + e], Wout[3 * EE + e]);
        }
        return;
    }

    int warp = threadIdx.x >> 5, lane = threadIdx.x & 31;
    int tok = (blockIdx.x - 1) * 8 + warp;

    float p[12];
    #pragma unroll
    for (int r = 0; r < 12; r++) p[r] = 0.f;

    const float4* xr4 = reinterpret_cast<const float4*>(x + (size_t)tok * EE);
    const float4* Wq4 = reinterpret_cast<const float4*>(Wq);
    const float4* Wk4 = reinterpret_cast<const float4*>(Wk);
    const float4* Wv4 = reinterpret_cast<const float4*>(Wv);

    #pragma unroll
    for (int k = 0; k < 4; k++) {
        int e4 = k * 32 + lane;        // float4 index into x row
        float4 xv = __ldg(xr4 + e4);
        float xs[4] = { xv.x, xv.y, xv.z, xv.w };
        int eb = e4 * 4;
        #pragma unroll
        for (int t = 0; t < 4; t++) {
            float xt = xs[t];
            float4 wq = __ldg(Wq4 + eb + t);
            float4 wk = __ldg(Wk4 + eb + t);
            float4 wv = __ldg(Wv4 + eb + t);
            p[0] = fmaf(xt, wq.x, p[0]);  p[1] = fmaf(xt, wq.y, p[1]);
            p[2] = fmaf(xt, wq.z, p[2]);  p[3] = fmaf(xt, wq.w, p[3]);
            p[4] = fmaf(xt, wk.x, p[4]);  p[5] = fmaf(xt, wk.y, p[5]);
            p[6] = fmaf(xt, wk.z, p[6]);  p[7] = fmaf(xt, wk.w, p[7]);
            p[8] = fmaf(xt, wv.x, p[8]);  p[9] = fmaf(xt, wv.y, p[9]);
            p[10] = fmaf(xt, wv.z, p[10]); p[11] = fmaf(xt, wv.w, p[11]);
        }
    }
    #pragma unroll
    for (int r = 0; r < 12; r++)
        #pragma unroll
        for (int o = 16; o > 0; o >>= 1)
            p[r] += __shfl_xor_sync(0xFFFFFFFFu, p[r], o);

    if (lane == 0) {
        float* gq = (float*)g_q4;
        float* gk = (float*)g_k4;
        float* gv = (float*)g_v4;
        // store tanh(q), tanh(k): main uses tanh(u+v) = (tu+tv)/(1+tu*tv)
        gq[tok * 4 + 0] = ftanh(ftanh(p[0] + bq[0]));
        gq[tok * 4 + 1] = ftanh(ftanh(p[1] + bq[1]));
        gq[tok * 4 + 2] = ftanh(ftanh(p[2] + bq[2]));
        gq[tok * 4 + 3] = ftanh(ftanh(p[3] + bq[3]));
        gk[tok * 4 + 0] = ftanh(ftanh(p[4] + bk[0]));
        gk[tok * 4 + 1] = ftanh(ftanh(p[5] + bk[1]));
        gk[tok * 4 + 2] = ftanh(ftanh(p[6] + bk[2]));
        gk[tok * 4 + 3] = ftanh(ftanh(p[7] + bk[3]));
        gv[tok * 4 + 0] = p[8]  + bv[0];
        gv[tok * 4 + 1] = p[9]  + bv[1];
        gv[tok * 4 + 2] = p[10] + bv[2];
        gv[tok * 4 + 3] = p[11] + bv[3];
    }
}

// ============================================================
// Kernel 2: fused scores + softmax + attend + output projection.
// One block per row, 512 threads, one pair per thread.
// C in __constant__; tanh-addition identity; no max-subtraction
// (score analytically bounded in [-2,2]); float4 Wout epilogue.
// ============================================================
__global__ __launch_bounds__(512)
void main_kernel(const float* __restrict__ bout,
                 float* __restrict__ out, float* __restrict__ attn_out) {
    __shared__ float4 Ksh[SS];
    __shared__ float4 Vsh[SS];
    __shared__ float  red[16 * 5];
    __shared__ float  fin[5];

    int blk = blockIdx.x;          // b*512 + i
    int b   = blk >> 9;
    int tid = threadIdx.x;

    Ksh[tid] = g_k4[b * SS + tid];
    Vsh[tid] = g_v4[b * SS + tid];
    float4 qv = g_q4[blk];         // tanh(q)
    __syncthreads();

    float4 kv = Ksh[tid];          // tanh(k)

    // a = tanh(q + k) = (tq + tk) / (1 + tq*tk)   (exact identity)
    float a0 = __fdividef(qv.x + kv.x, fmaf(qv.x, kv.x, 1.f));
    float a1 = __fdividef(qv.y + kv.y, fmaf(qv.y, kv.y, 1.f));
    float a2 = __fdividef(qv.z + kv.z, fmaf(qv.z, kv.z, 1.f));
    float a3 = __fdividef(qv.w + kv.w, fmaf(qv.w, kv.w, 1.f));

    float c0, s0, c1, s1, c2, s2, c3, s3;
    __sincosf(a0, &s0, &c0);
    __sincosf(a1, &s1, &c1);
    __sincosf(a2, &s2, &c2);
    __sincosf(a3, &s3, &c3);
    float u0[2] = {c0, s0}, u1[2] = {c1, s1}, u2[2] = {c2, s2};

    // score = sum_m C[m] * prod_w u_w[m_w], scale pre-folded into C.
    float score = 0.f;
    #pragma unroll
    for (int m0 = 0; m0 < 3; m0++) {
        float t1 = 0.f;
        #pragma unroll
        for (int m1 = 0; m1 < 3; m1++) {
            float t2 = 0.f;
            #pragma unroll
            for (int m2 = 0; m2 < 3; m2++) {
                float4 c = c_C4[(m0 * 3 + m1) * 3 + m2];
                float t3 = fmaf(c.x, c3, fmaf(c.y, s3, c.z));
                t2 = (m2 == 2) ? (t2 + t3) : fmaf(t3, u2[m2], t2);
            }
            t1 = (m1 == 2) ? (t1 + t2) : fmaf(t2, u1[m1], t1);
        }
        score = (m0 == 2) ? (score + t1) : fmaf(t1, u0[m0], score);
    }

    float ej = __expf(score);        // no max shift needed: score in [-2,2]
    float4 vv = Vsh[tid];

    // ---- single fused 5-way block reduction: {sum e, sum e*v0..v3} ----
    float vals[5] = { ej, ej * vv.x, ej * vv.y, ej * vv.z, ej * vv.w };
    #pragma unroll
    for (int r = 0; r < 5; r++)
        #pragma unroll
        for (int o = 16; o > 0; o >>= 1)
            vals[r] += __shfl_xor_sync(0xFFFFFFFFu, vals[r], o);

    int lane = tid & 31, warp = tid >> 5;
    if (lane == 0) {
        #pragma unroll
        for (int r = 0; r < 5; r++) red[warp * 5 + r] = vals[r];
    }
    __syncthreads();
    if (tid < 5) {
        float s = 0.f;
        #pragma unroll
        for (int w = 0; w < 16; w++) s += red[w * 5 + tid];
        fin[tid] = s;
    }
    __syncthreads();

    float inv = __fdividef(1.f, fin[0]);
    attn_out[(size_t)blk * SS + tid] = ej * inv;

    float aw0 = fin[1] * inv;
    float aw1 = fin[2] * inv;
    float aw2 = fin[3] * inv;
    float aw3 = fin[4] * inv;

    // out[b,i,e] = sum_w attended[w] * WoutT[e][w] + bout[e]   (e = tid)
    float4 wo = g_Wo4[tid];
    float o = bout[tid];
    o = fmaf(aw0, wo.x, o);
    o = fmaf(aw1, wo.y, o);
    o = fmaf(aw2, wo.z, o);
    o = fmaf(aw3, wo.w, o);
    out[(size_t)blk * EE + tid] = o;
}

// ============================================================
extern "C" void kernel_launch(void* const* d_in, const int* in_sizes, int n_in,
                              void* d_out, int out_size) {
    const float* x    = (const float*)d_in[0];
    const float* Wq   = (const float*)d_in[1];
    const float* bq   = (const float*)d_in[2];
    const float* Wk   = (const float*)d_in[3];
    const float* bk   = (const float*)d_in[4];
    const float* Wv   = (const float*)d_in[5];
    const float* bv   = (const float*)d_in[6];
    const float* qw   = (const float*)d_in[7];
    const float* Wout = (const float*)d_in[8];
    const float* bout = (const float*)d_in[9];

    float* out  = (float*)d_out;
    float* attn = out + OUT_ELEMS;

    // block 0 = setup warp + Wout transpose; blocks 1..256 = qkv
    qkv_kernel<<<NTOK / 8 + 1, 256>>>(x, Wq, bq, Wk, bk, Wv, bv, qw, Wout);

    // stage C tensor into constant memory (device-to-device async copy,
    // graph-capturable; ordered after qkv_kernel on the same stream)
    void* c_src = nullptr;
    cudaGetSymbolAddress(&c_src, g_C4);
    cudaMemcpyToSymbolAsync(c_C4, c_src, sizeof(float4) * 27, 0,
                            cudaMemcpyDeviceToDevice);

    main_kernel<<<NTOK, 512>>>(bout, out, attn);
}